// round 11
// baseline (speedup 1.0000x reference)
#include <cuda_runtime.h>
#include <math.h>

// Fixed shapes: kernels [1,8192,256] f32, categories [1,8192] i32, scores [1,8192] f32
#define NN   8192
#define DD   256
#define D4   64
#define NC   128
#define TS   32
#define H4   8           // head = first 32 dims = 8 float4
#define PH   9           // head pitch in float4 (8+1 -> conflict-free)
#define THRESH 0.95f
#define EPSN 1e-8f
#define OCC  4
#define GRID (148 * OCC) // all blocks co-resident (required for gbar)
#define NT   256

// Output: ALL float32, concatenated:
//   fused [NN*DD] @0, cats [NN] @NN*DD, scores [NN] @NN*DD+NN, keep [NN] @NN*DD+2*NN

// ---------------- device scratch ----------------
// Invariant: g_cnt[], g_dirty ZERO at entry (static init; re-zeroed every run).
__device__ float g_invn[NN];
__device__ float g_tail[NN];          // ||normalized tail (dims 32..255)||
__device__ int   g_cnt[NC];           // scatter fill counter (== final counts)
__device__ int   g_buck[NC * NN];     // fixed-base member buckets
__device__ int   g_claim[NN];
__device__ int   g_cnt2[NN];
__device__ int   g_dirty;
__device__ unsigned g_bar_cnt = 0;
__device__ unsigned g_bar_gen = 0;    // monotonically increasing across replays (harmless)

static __device__ __forceinline__ int clamp_cat(int ci) {
    if (ci < 0) ci = 0;
    if (ci > NC - 1) ci = NC - 1;
    return ci;
}

static __device__ __forceinline__ unsigned ld_acq(const unsigned* p) {
    unsigned v;
    asm volatile("ld.acquire.gpu.u32 %0, [%1];" : "=r"(v) : "l"(p) : "memory");
    return v;
}

// Grid-wide barrier. Safe because all GRID blocks are co-resident.
static __device__ __forceinline__ void gbar() {
    __threadfence();
    __syncthreads();
    if (threadIdx.x == 0) {
        unsigned gen = ld_acq(&g_bar_gen);
        if (atomicInc(&g_bar_cnt, GRID - 1) == GRID - 1) {
            atomicAdd(&g_bar_gen, 1u);
        } else {
            while (ld_acq(&g_bar_gen) == gen) { __nanosleep(32); }
        }
        __threadfence();
    }
    __syncthreads();
}

__global__ void __launch_bounds__(NT, OCC) k_all(const float* __restrict__ kin,
                                                 const int* __restrict__ cat,
                                                 const float* __restrict__ scores,
                                                 float* __restrict__ out) {
    extern __shared__ float4 sm[];      // sA[TS*PH] + sB[TS*PH]
    const int t = threadIdx.x;
    const int lane = t & 31, wp = t >> 5;
    const float4* k4g = (const float4*)kin;

    // ---------- P0: row norms + tail norms + direct bucket scatter (2 rows/warp) ----------
    {
        int r0 = blockIdx.x * 16 + wp * 2;      // 592*16 = 9472 >= 8192
        if (r0 < NN) {
            int r1 = r0 + 1;
            float4 a0 = k4g[r0 * D4 + lane];
            float4 b0 = k4g[r0 * D4 + 32 + lane];
            float4 a1 = k4g[r1 * D4 + lane];
            float4 b1 = k4g[r1 * D4 + 32 + lane];
            float asq0 = a0.x*a0.x + a0.y*a0.y + a0.z*a0.z + a0.w*a0.w;
            float bsq0 = b0.x*b0.x + b0.y*b0.y + b0.z*b0.z + b0.w*b0.w;
            float asq1 = a1.x*a1.x + a1.y*a1.y + a1.z*a1.z + a1.w*a1.w;
            float bsq1 = b1.x*b1.x + b1.y*b1.y + b1.z*b1.z + b1.w*b1.w;
            float s0 = asq0 + bsq0, s1 = asq1 + bsq1;
            float h0 = (lane < H4) ? asq0 : 0.0f;   // head = dims 0..31
            float h1 = (lane < H4) ? asq1 : 0.0f;
            #pragma unroll
            for (int o = 16; o; o >>= 1) {
                s0 += __shfl_xor_sync(0xFFFFFFFFu, s0, o);
                s1 += __shfl_xor_sync(0xFFFFFFFFu, s1, o);
                h0 += __shfl_xor_sync(0xFFFFFFFFu, h0, o);
                h1 += __shfl_xor_sync(0xFFFFFFFFu, h1, o);
            }
            if (lane < 2) {
                int row = (lane == 0) ? r0 : r1;
                float s = (lane == 0) ? s0 : s1;
                float h = (lane == 0) ? h0 : h1;
                float invn = 1.0f / fmaxf(sqrtf(s), EPSN);
                g_invn[row]  = invn;
                float headfrac = h * invn * invn;
                g_tail[row]  = sqrtf(fmaxf(0.0f, 1.0f - headfrac));
                g_claim[row] = row;
                g_cnt2[row]  = 0;
                int ci = clamp_cat(cat[row]);
                int pos = atomicAdd(&g_cnt[ci], 1);
                g_buck[ci * NN + pos] = row;
            }
        }
    }
    gbar();

    // ---------- P3: pair tiles, static assignment + binary-search decode ----------
    {
        __shared__ int s_cnt[NC], s_tp[NC + 1];
        __shared__ int wsp[8];
        {
            int c = 0, tp = 0;
            if (t < NC) {
                c = __ldcg(&g_cnt[t]);
                int T = (c + TS - 1) / TS;
                tp = T * (T + 1) / 2;
                s_cnt[t] = c;
            }
            int ip = tp;
            #pragma unroll
            for (int o = 1; o < 32; o <<= 1) {
                int v = __shfl_up_sync(0xFFFFFFFFu, ip, o);
                if (lane >= o) ip += v;
            }
            if (lane == 31 && wp < 4) wsp[wp] = ip;
            __syncthreads();
            if (t < NC) {
                int op = 0;
                #pragma unroll
                for (int ww = 0; ww < 4; ww++)
                    if (ww < wp) op += wsp[ww];
                s_tp[t] = ip + op - tp;   // exclusive prefix
                if (t == NC - 1) s_tp[NC] = ip + op;
            }
            __syncthreads();
        }
        const int total = s_tp[NC];

        float4* sA = sm;
        float4* sB = sm + TS * PH;
        __shared__ int gA[TS], gB[TS];
        __shared__ float sTailA[TS], sTailB[TS];

        for (int w = blockIdx.x; w < total; w += GRID) {
            int lo = 0, hi = NC;
            #pragma unroll
            for (int it = 0; it < 7; it++) {
                int mid = (lo + hi) >> 1;
                if (w >= s_tp[mid]) lo = mid; else hi = mid;
            }
            int c = lo;
            int p = w - s_tp[c];
            int cc = s_cnt[c];
            int T = (cc + TS - 1) / TS;
            int ta = 0;
            while (p >= T - ta) { p -= T - ta; ta++; }
            int tb = ta + p;
            int rowA = c * NN + ta * TS;
            int rowB = c * NN + tb * TS;
            int na = min(TS, cc - ta * TS);
            int nb = min(TS, cc - tb * TS);

            if (t < TS) {
                int a = (t < na) ? __ldcg(&g_buck[rowA + t]) : -1;
                int b = (t < nb) ? __ldcg(&g_buck[rowB + t]) : -1;
                gA[t] = a; gB[t] = b;
                sTailA[t] = (a >= 0) ? g_tail[a] : 0.0f;
                sTailB[t] = (b >= 0) ? g_tail[b] : 0.0f;
            }
            __syncthreads();

            // stage normalized 32-dim heads: exactly 1 float4 per thread
            {
                int r = t >> 3, k4 = t & 7;
                float4 va = make_float4(0.f, 0.f, 0.f, 0.f);
                int g = gA[r];
                if (g >= 0) {
                    va = k4g[g * D4 + k4];
                    float sc = g_invn[g];
                    va.x *= sc; va.y *= sc; va.z *= sc; va.w *= sc;
                }
                sA[r * PH + k4] = va;
                float4 vb = make_float4(0.f, 0.f, 0.f, 0.f);
                g = gB[r];
                if (g >= 0) {
                    vb = k4g[g * D4 + k4];
                    float sc = g_invn[g];
                    vb.x *= sc; vb.y *= sc; vb.z *= sc; vb.w *= sc;
                }
                sB[r * PH + k4] = vb;
            }
            __syncthreads();

            int ra = t & 31;
            int rq = t >> 5;
            float a0 = 0.f, a1 = 0.f, a2 = 0.f, a3 = 0.f;
            #pragma unroll
            for (int k4 = 0; k4 < H4; k4++) {
                float4 a  = sA[ra * PH + k4];
                float4 b0 = sB[(rq      ) * PH + k4];
                float4 b1 = sB[(rq +  8 ) * PH + k4];
                float4 b2 = sB[(rq + 16 ) * PH + k4];
                float4 b3 = sB[(rq + 24 ) * PH + k4];
                a0 += a.x * b0.x + a.y * b0.y + a.z * b0.z + a.w * b0.w;
                a1 += a.x * b1.x + a.y * b1.y + a.z * b1.z + a.w * b1.w;
                a2 += a.x * b2.x + a.y * b2.y + a.z * b2.z + a.w * b2.w;
                a3 += a.x * b3.x + a.y * b3.y + a.z * b3.z + a.w * b3.w;
            }
            if (ra < na) {
                int ga = gA[ra];
                float tA = sTailA[ra];
                float accs[4] = {a0, a1, a2, a3};
                #pragma unroll
                for (int j = 0; j < 4; j++) {
                    int rb = rq + 8 * j;
                    if (rb < nb) {
                        int gb = gB[rb];
                        if (gb != ga && accs[j] + tA * sTailB[rb] >= THRESH) {
                            // C-S bound passed: exact full 256-dim dot from L2
                            float invA = g_invn[ga], invB = g_invn[gb];
                            float d = 0.0f;
                            for (int k = 0; k < D4; k++) {
                                float4 x = __ldg(&k4g[ga * D4 + k]);
                                float4 y = __ldg(&k4g[gb * D4 + k]);
                                d += x.x * y.x + x.y * y.y + x.z * y.z + x.w * y.w;
                            }
                            if (d * invA * invB >= THRESH) {
                                int lo2 = min(ga, gb), hi2 = max(ga, gb);
                                atomicMin(&g_claim[hi2], lo2);
                                g_dirty = 1;
                            }
                        }
                    }
                }
            }
            __syncthreads();
        }
    }
    gbar();

    // dirty is FINAL and uniform across blocks here
    const int dirty = __ldcg(&g_dirty);

    if (!dirty) {
        // FAST PATH: everything kept, fused == kernels. Pure streaming copy;
        // stores drain at kernel exit (no fence after this point).
        const float4* src = k4g;
        float4* dst = (float4*)out;
        int gtid = blockIdx.x * NT + t;
        int nthr = GRID * NT;
        for (int i = gtid; i < NN * D4; i += nthr)
            dst[i] = src[i];
        if (gtid < NN) {
            out[NN * DD + gtid]          = (float)cat[gtid];
            out[NN * DD + NN + gtid]     = scores[gtid];
            out[NN * DD + 2 * NN + gtid] = 1.0f;
        }
        if (blockIdx.x == 1 && t < NC) g_cnt[t] = 0;    // restore invariant
        return;
    }

    // ---------- SLOW PATH (rare): exact semantics with cnt2 ----------
    {
        int idx = blockIdx.x * NT + t;
        if (idx < NN) {
            int c = __ldcg(&g_claim[idx]);
            bool keep = (c == idx);
            out[NN * DD + idx]          = keep ? (float)cat[idx] : -1.0f;
            out[NN * DD + NN + idx]     = keep ? scores[idx] : 0.0f;
            out[NN * DD + 2 * NN + idx] = keep ? 1.0f : 0.0f;
            bool owner_kept = (__ldcg(&g_claim[c]) == c);
            if (owner_kept) atomicAdd(&g_cnt2[c], 1);
            if (!keep) {
                float4 z = make_float4(0.f, 0.f, 0.f, 0.f);
                float4* o4 = (float4*)out;
                #pragma unroll 4
                for (int k = 0; k < D4; k++) o4[idx * D4 + k] = z;
                if (owner_kept) {
                    #pragma unroll 4
                    for (int k = 0; k < D4; k++) o4[c * D4 + k] = z;
                }
            }
        }
    }
    gbar();
    {
        for (int j = blockIdx.x * 8 + wp; j < NN; j += GRID * 8) {
            float4 v0 = k4g[j * D4 + lane];
            float4 v1 = k4g[j * D4 + 32 + lane];
            int i = 0, n = 0, ok = 0;
            if (lane == 0) {
                i = __ldcg(&g_claim[j]);
                ok = (__ldcg(&g_claim[i]) == i);
                if (ok) n = __ldcg(&g_cnt2[i]);
            }
            i  = __shfl_sync(0xFFFFFFFFu, i, 0);
            ok = __shfl_sync(0xFFFFFFFFu, ok, 0);
            n  = __shfl_sync(0xFFFFFFFFu, n, 0);
            if (!ok) continue;
            if (n == 1) {
                float4* o4 = (float4*)out;
                o4[i * D4 + lane]      = v0;
                o4[i * D4 + 32 + lane] = v1;
            } else {
                float w = 1.0f / (float)n;
                atomicAdd(&out[i * DD + lane * 4 + 0],       v0.x * w);
                atomicAdd(&out[i * DD + lane * 4 + 1],       v0.y * w);
                atomicAdd(&out[i * DD + lane * 4 + 2],       v0.z * w);
                atomicAdd(&out[i * DD + lane * 4 + 3],       v0.w * w);
                atomicAdd(&out[i * DD + 128 + lane * 4 + 0], v1.x * w);
                atomicAdd(&out[i * DD + 128 + lane * 4 + 1], v1.y * w);
                atomicAdd(&out[i * DD + 128 + lane * 4 + 2], v1.z * w);
                atomicAdd(&out[i * DD + 128 + lane * 4 + 3], v1.w * w);
            }
        }
        // restore invariants (g_dirty consumed by all blocks before previous gbar)
        if (blockIdx.x == 0 && t == 0) g_dirty = 0;
        if (blockIdx.x == 1 && t < NC) g_cnt[t] = 0;
    }
}

// ---------------- launch ----------------
extern "C" void kernel_launch(void* const* d_in, const int* in_sizes, int n_in,
                              void* d_out, int out_size) {
    const float* kin    = (const float*)d_in[0];
    const int*   cat    = (const int*)d_in[1];
    const float* scores = (const float*)d_in[2];
    float*       out    = (float*)d_out;

    (void)in_sizes; (void)n_in; (void)out_size;

    const int smem = 2 * TS * PH * (int)sizeof(float4);  // 9,216 B
    cudaFuncSetAttribute(k_all, cudaFuncAttributeMaxDynamicSharedMemorySize, smem);

    k_all<<<GRID, NT, smem>>>(kin, cat, scores, out);
}

// round 12
// speedup vs baseline: 1.4651x; 1.4651x over previous
#include <cuda_runtime.h>
#include <math.h>

// Fixed shapes: kernels [1,8192,256] f32, categories [1,8192] i32, scores [1,8192] f32
#define NN   8192
#define DD   256
#define D4   64
#define NC   128
#define TS   32
#define H4   16          // head = first 64 dims = 16 float4 (DO NOT shrink: C-S bound needs 64 dims)
#define PH   17          // head pitch in float4 (16+1 -> conflict-free)
#define THRESH 0.95f
#define EPSN 1e-8f
#define OCC  4
#define GRID (148 * OCC) // all blocks co-resident (required for gbar)
#define NT   256

// Output: ALL float32, concatenated:
//   fused [NN*DD] @0, cats [NN] @NN*DD, scores [NN] @NN*DD+NN, keep [NN] @NN*DD+2*NN

// ---------------- device scratch ----------------
// Invariant: g_cnt[], g_dirty ZERO at entry (static init; re-zeroed every run).
__device__ float g_invn[NN];
__device__ float g_tail[NN];          // ||normalized tail (dims 64..255)||
__device__ int   g_cnt[NC];           // scatter fill counter (== final counts)
__device__ int   g_buck[NC * NN];     // fixed-base member buckets
__device__ int   g_claim[NN];
__device__ int   g_cnt2[NN];
__device__ int   g_dirty;
__device__ unsigned g_bar_cnt = 0;
__device__ unsigned g_bar_gen = 0;    // monotonically increasing across replays (harmless)

static __device__ __forceinline__ int clamp_cat(int ci) {
    if (ci < 0) ci = 0;
    if (ci > NC - 1) ci = NC - 1;
    return ci;
}

static __device__ __forceinline__ unsigned ld_acq(const unsigned* p) {
    unsigned v;
    asm volatile("ld.acquire.gpu.u32 %0, [%1];" : "=r"(v) : "l"(p) : "memory");
    return v;
}

// Grid-wide barrier. Safe because all GRID blocks are co-resident.
static __device__ __forceinline__ void gbar() {
    __threadfence();
    __syncthreads();
    if (threadIdx.x == 0) {
        unsigned gen = ld_acq(&g_bar_gen);
        if (atomicInc(&g_bar_cnt, GRID - 1) == GRID - 1) {
            atomicAdd(&g_bar_gen, 1u);
        } else {
            while (ld_acq(&g_bar_gen) == gen) { __nanosleep(32); }
        }
        __threadfence();
    }
    __syncthreads();
}

__global__ void __launch_bounds__(NT, OCC) k_all(const float* __restrict__ kin,
                                                 const int* __restrict__ cat,
                                                 const float* __restrict__ scores,
                                                 float* __restrict__ out) {
    extern __shared__ float4 sm[];      // 4 tiles x TS*PH
    const int t = threadIdx.x;
    const int lane = t & 31, wp = t >> 5;
    const float4* k4g = (const float4*)kin;

    // ---------- P0: row norms + tail norms + direct bucket scatter (2 rows/warp) ----------
    {
        int r0 = blockIdx.x * 16 + wp * 2;      // 592*16 = 9472 >= 8192
        if (r0 < NN) {
            int r1 = r0 + 1;
            float4 a0 = k4g[r0 * D4 + lane];
            float4 b0 = k4g[r0 * D4 + 32 + lane];
            float4 a1 = k4g[r1 * D4 + lane];
            float4 b1 = k4g[r1 * D4 + 32 + lane];
            float asq0 = a0.x*a0.x + a0.y*a0.y + a0.z*a0.z + a0.w*a0.w;
            float bsq0 = b0.x*b0.x + b0.y*b0.y + b0.z*b0.z + b0.w*b0.w;
            float asq1 = a1.x*a1.x + a1.y*a1.y + a1.z*a1.z + a1.w*a1.w;
            float bsq1 = b1.x*b1.x + b1.y*b1.y + b1.z*b1.z + b1.w*b1.w;
            float s0 = asq0 + bsq0, s1 = asq1 + bsq1;
            float h0 = (lane < H4) ? asq0 : 0.0f;   // head = dims 0..63
            float h1 = (lane < H4) ? asq1 : 0.0f;
            #pragma unroll
            for (int o = 16; o; o >>= 1) {
                s0 += __shfl_xor_sync(0xFFFFFFFFu, s0, o);
                s1 += __shfl_xor_sync(0xFFFFFFFFu, s1, o);
                h0 += __shfl_xor_sync(0xFFFFFFFFu, h0, o);
                h1 += __shfl_xor_sync(0xFFFFFFFFu, h1, o);
            }
            if (lane < 2) {
                int row = (lane == 0) ? r0 : r1;
                float s = (lane == 0) ? s0 : s1;
                float h = (lane == 0) ? h0 : h1;
                float invn = 1.0f / fmaxf(sqrtf(s), EPSN);
                g_invn[row]  = invn;
                float headfrac = h * invn * invn;
                g_tail[row]  = sqrtf(fmaxf(0.0f, 1.0f - headfrac));
                g_claim[row] = row;
                g_cnt2[row]  = 0;
                int ci = clamp_cat(cat[row]);
                int pos = atomicAdd(&g_cnt[ci], 1);
                g_buck[ci * NN + pos] = row;
            }
        }
    }
    gbar();

    // ---------- P3: pair tiles, TWO work items per block iteration ----------
    {
        __shared__ int s_cnt[NC], s_tp[NC + 1];
        __shared__ int wsp[8];
        {
            int c = 0, tp = 0;
            if (t < NC) {
                c = __ldcg(&g_cnt[t]);
                int T = (c + TS - 1) / TS;
                tp = T * (T + 1) / 2;
                s_cnt[t] = c;
            }
            int ip = tp;
            #pragma unroll
            for (int o = 1; o < 32; o <<= 1) {
                int v = __shfl_up_sync(0xFFFFFFFFu, ip, o);
                if (lane >= o) ip += v;
            }
            if (lane == 31 && wp < 4) wsp[wp] = ip;
            __syncthreads();
            if (t < NC) {
                int op = 0;
                #pragma unroll
                for (int ww = 0; ww < 4; ww++)
                    if (ww < wp) op += wsp[ww];
                s_tp[t] = ip + op - tp;   // exclusive prefix
                if (t == NC - 1) s_tp[NC] = ip + op;
            }
            __syncthreads();
        }
        const int total = s_tp[NC];

        float4* sT[4] = { sm, sm + TS * PH, sm + 2 * TS * PH, sm + 3 * TS * PH };
        __shared__ int   gL[4][TS];
        __shared__ float gTl[4][TS];

        for (int w1 = blockIdx.x * 2; w1 < total; w1 += GRID * 2) {
            const int w2 = w1 + 1;
            const bool has2 = (w2 < total);

            // decode both items redundantly on all threads
            int rowA[2], rowB[2], na[2], nb[2];
            #pragma unroll
            for (int it2 = 0; it2 < 2; it2++) {
                int w = (it2 == 0) ? w1 : w2;
                if (it2 == 1 && !has2) { rowA[1] = rowA[0]; rowB[1] = rowB[0]; na[1] = 0; nb[1] = 0; break; }
                int lo = 0, hi = NC;
                #pragma unroll
                for (int s = 0; s < 7; s++) {
                    int mid = (lo + hi) >> 1;
                    if (w >= s_tp[mid]) lo = mid; else hi = mid;
                }
                int c = lo;
                int p = w - s_tp[c];
                int cc = s_cnt[c];
                int T = (cc + TS - 1) / TS;
                int ta = 0;
                while (p >= T - ta) { p -= T - ta; ta++; }
                int tb = ta + p;
                rowA[it2] = c * NN + ta * TS;
                rowB[it2] = c * NN + tb * TS;
                na[it2] = min(TS, cc - ta * TS);
                nb[it2] = min(TS, cc - tb * TS);
            }

            // gather: 4 warps fetch the 4 member lists in parallel
            if (wp < 4) {
                int it2 = wp >> 1;                 // 0: item1, 1: item2
                int isB = wp & 1;
                int n   = isB ? nb[it2] : na[it2];
                int row = isB ? rowB[it2] : rowA[it2];
                int g = (lane < n) ? __ldcg(&g_buck[row + lane]) : -1;
                gL[wp][lane]  = g;
                gTl[wp][lane] = (g >= 0) ? g_tail[g] : 0.0f;
            }
            __syncthreads();

            // stage all (up to) 4 tiles back-to-back (loads overlap)
            const int ntiles = has2 ? 4 : 2;
            for (int tile = 0; tile < ntiles; tile++) {
                const int* gl = gL[tile];
                float4* sd = sT[tile];
                #pragma unroll
                for (int i = t; i < TS * H4; i += NT) {
                    int r = i >> 4, k4 = i & 15;
                    float4 v = make_float4(0.f, 0.f, 0.f, 0.f);
                    int g = gl[r];
                    if (g >= 0) {
                        v = k4g[g * D4 + k4];
                        float sc = g_invn[g];
                        v.x *= sc; v.y *= sc; v.z *= sc; v.w *= sc;
                    }
                    sd[r * PH + k4] = v;
                }
            }
            __syncthreads();

            // dots: item 1 then item 2
            const int ra = t & 31;
            const int rq = t >> 5;
            #pragma unroll
            for (int it2 = 0; it2 < 2; it2++) {
                if (it2 == 1 && !has2) break;
                const float4* sA = sT[it2 * 2];
                const float4* sB = sT[it2 * 2 + 1];
                float a0 = 0.f, a1 = 0.f, a2 = 0.f, a3 = 0.f;
                #pragma unroll
                for (int k4 = 0; k4 < H4; k4++) {
                    float4 a  = sA[ra * PH + k4];
                    float4 b0 = sB[(rq      ) * PH + k4];
                    float4 b1 = sB[(rq +  8 ) * PH + k4];
                    float4 b2 = sB[(rq + 16 ) * PH + k4];
                    float4 b3 = sB[(rq + 24 ) * PH + k4];
                    a0 += a.x * b0.x + a.y * b0.y + a.z * b0.z + a.w * b0.w;
                    a1 += a.x * b1.x + a.y * b1.y + a.z * b1.z + a.w * b1.w;
                    a2 += a.x * b2.x + a.y * b2.y + a.z * b2.z + a.w * b2.w;
                    a3 += a.x * b3.x + a.y * b3.y + a.z * b3.z + a.w * b3.w;
                }
                if (ra < na[it2]) {
                    int ga = gL[it2 * 2][ra];
                    float tA = gTl[it2 * 2][ra];
                    float accs[4] = {a0, a1, a2, a3};
                    #pragma unroll
                    for (int j = 0; j < 4; j++) {
                        int rb = rq + 8 * j;
                        if (rb < nb[it2]) {
                            int gb = gL[it2 * 2 + 1][rb];
                            if (gb != ga && accs[j] + tA * gTl[it2 * 2 + 1][rb] >= THRESH) {
                                // C-S bound passed: exact full 256-dim dot from L2
                                float invA = g_invn[ga], invB = g_invn[gb];
                                float d = 0.0f;
                                for (int k = 0; k < D4; k++) {
                                    float4 x = __ldg(&k4g[ga * D4 + k]);
                                    float4 y = __ldg(&k4g[gb * D4 + k]);
                                    d += x.x * y.x + x.y * y.y + x.z * y.z + x.w * y.w;
                                }
                                if (d * invA * invB >= THRESH) {
                                    int lo2 = min(ga, gb), hi2 = max(ga, gb);
                                    atomicMin(&g_claim[hi2], lo2);
                                    g_dirty = 1;
                                }
                            }
                        }
                    }
                }
            }
            __syncthreads();
        }
    }
    gbar();

    // dirty is FINAL and uniform across blocks here
    const int dirty = __ldcg(&g_dirty);

    if (!dirty) {
        // FAST PATH: everything kept, fused == kernels. Streaming copy;
        // stores drain at kernel exit (no fence after this point).
        const float4* src = k4g;
        float4* dst = (float4*)out;
        int gtid = blockIdx.x * NT + t;
        int nthr = GRID * NT;
        for (int i = gtid; i < NN * D4; i += nthr)
            dst[i] = src[i];
        if (gtid < NN) {
            out[NN * DD + gtid]          = (float)cat[gtid];
            out[NN * DD + NN + gtid]     = scores[gtid];
            out[NN * DD + 2 * NN + gtid] = 1.0f;
        }
        if (blockIdx.x == 1 && t < NC) g_cnt[t] = 0;    // restore invariant
        return;
    }

    // ---------- SLOW PATH (rare): exact semantics with cnt2 ----------
    {
        int idx = blockIdx.x * NT + t;
        if (idx < NN) {
            int c = __ldcg(&g_claim[idx]);
            bool keep = (c == idx);
            out[NN * DD + idx]          = keep ? (float)cat[idx] : -1.0f;
            out[NN * DD + NN + idx]     = keep ? scores[idx] : 0.0f;
            out[NN * DD + 2 * NN + idx] = keep ? 1.0f : 0.0f;
            bool owner_kept = (__ldcg(&g_claim[c]) == c);
            if (owner_kept) atomicAdd(&g_cnt2[c], 1);
            if (!keep) {
                float4 z = make_float4(0.f, 0.f, 0.f, 0.f);
                float4* o4 = (float4*)out;
                #pragma unroll 4
                for (int k = 0; k < D4; k++) o4[idx * D4 + k] = z;
                if (owner_kept) {
                    #pragma unroll 4
                    for (int k = 0; k < D4; k++) o4[c * D4 + k] = z;
                }
            }
        }
    }
    gbar();
    {
        for (int j = blockIdx.x * 8 + wp; j < NN; j += GRID * 8) {
            float4 v0 = k4g[j * D4 + lane];
            float4 v1 = k4g[j * D4 + 32 + lane];
            int i = 0, n = 0, ok = 0;
            if (lane == 0) {
                i = __ldcg(&g_claim[j]);
                ok = (__ldcg(&g_claim[i]) == i);
                if (ok) n = __ldcg(&g_cnt2[i]);
            }
            i  = __shfl_sync(0xFFFFFFFFu, i, 0);
            ok = __shfl_sync(0xFFFFFFFFu, ok, 0);
            n  = __shfl_sync(0xFFFFFFFFu, n, 0);
            if (!ok) continue;
            if (n == 1) {
                float4* o4 = (float4*)out;
                o4[i * D4 + lane]      = v0;
                o4[i * D4 + 32 + lane] = v1;
            } else {
                float w = 1.0f / (float)n;
                atomicAdd(&out[i * DD + lane * 4 + 0],       v0.x * w);
                atomicAdd(&out[i * DD + lane * 4 + 1],       v0.y * w);
                atomicAdd(&out[i * DD + lane * 4 + 2],       v0.z * w);
                atomicAdd(&out[i * DD + lane * 4 + 3],       v0.w * w);
                atomicAdd(&out[i * DD + 128 + lane * 4 + 0], v1.x * w);
                atomicAdd(&out[i * DD + 128 + lane * 4 + 1], v1.y * w);
                atomicAdd(&out[i * DD + 128 + lane * 4 + 2], v1.z * w);
                atomicAdd(&out[i * DD + 128 + lane * 4 + 3], v1.w * w);
            }
        }
        // restore invariants (g_dirty consumed by all blocks before previous gbar)
        if (blockIdx.x == 0 && t == 0) g_dirty = 0;
        if (blockIdx.x == 1 && t < NC) g_cnt[t] = 0;
    }
}

// ---------------- launch ----------------
extern "C" void kernel_launch(void* const* d_in, const int* in_sizes, int n_in,
                              void* d_out, int out_size) {
    const float* kin    = (const float*)d_in[0];
    const int*   cat    = (const int*)d_in[1];
    const float* scores = (const float*)d_in[2];
    float*       out    = (float*)d_out;

    (void)in_sizes; (void)n_in; (void)out_size;

    const int smem = 4 * TS * PH * (int)sizeof(float4);  // 34,816 B
    cudaFuncSetAttribute(k_all, cudaFuncAttributeMaxDynamicSharedMemorySize, smem);

    k_all<<<GRID, NT, smem>>>(kin, cat, scores, out);
}

// round 13
// speedup vs baseline: 1.6319x; 1.1139x over previous
#include <cuda_runtime.h>
#include <math.h>

// Fixed shapes: kernels [1,8192,256] f32, categories [1,8192] i32, scores [1,8192] f32
#define NN   8192
#define DD   256
#define D4   64
#define NC   128
#define TS   32
#define H4   16          // head = first 64 dims (DO NOT shrink: C-S bound needs 64 dims)
#define PH   17          // head pitch in float4 (16+1 -> conflict-free)
#define THRESH 0.95f
#define EPSN 1e-8f
#define OCC  4
#define GRID (148 * OCC) // all blocks co-resident (required for gbar)
#define NT   256

// Output: ALL float32, concatenated:
//   fused [NN*DD] @0, cats [NN] @NN*DD, scores [NN] @NN*DD+NN, keep [NN] @NN*DD+2*NN

// ---------------- device scratch ----------------
// Invariant: g_cnt[], g_dirty ZERO at entry (static init; re-zeroed every run).
__device__ float g_invn[NN];
__device__ float g_tail[NN];          // ||normalized tail (dims 64..255)||
__device__ int   g_cnt[NC];           // scatter fill counter (== final counts)
__device__ int   g_buck[NC * NN];     // fixed-base member buckets
__device__ int   g_claim[NN];
__device__ int   g_cnt2[NN];
__device__ int   g_dirty;
__device__ unsigned g_bar_cnt = 0;
__device__ unsigned g_bar_gen = 0;    // monotonically increasing across replays (harmless)

static __device__ __forceinline__ int clamp_cat(int ci) {
    if (ci < 0) ci = 0;
    if (ci > NC - 1) ci = NC - 1;
    return ci;
}

static __device__ __forceinline__ unsigned ld_acq(const unsigned* p) {
    unsigned v;
    asm volatile("ld.acquire.gpu.u32 %0, [%1];" : "=r"(v) : "l"(p) : "memory");
    return v;
}

// Grid-wide barrier. Safe because all GRID blocks are co-resident.
static __device__ __forceinline__ void gbar() {
    __threadfence();
    __syncthreads();
    if (threadIdx.x == 0) {
        unsigned gen = ld_acq(&g_bar_gen);
        if (atomicInc(&g_bar_cnt, GRID - 1) == GRID - 1) {
            atomicAdd(&g_bar_gen, 1u);
        } else {
            while (ld_acq(&g_bar_gen) == gen) { __nanosleep(32); }
        }
        __threadfence();
    }
    __syncthreads();
}

__global__ void __launch_bounds__(NT, OCC) k_all(const float* __restrict__ kin,
                                                 const int* __restrict__ cat,
                                                 const float* __restrict__ scores,
                                                 float* __restrict__ out) {
    extern __shared__ float4 sm[];      // sA[TS*PH] + sB[TS*PH]
    const int t = threadIdx.x;
    const int lane = t & 31, wp = t >> 5;
    const float4* k4g = (const float4*)kin;
    float4* out4 = (float4*)out;

    // ---------- P0: norms + tails + bucket scatter + DEFAULT OUTPUTS (copy is free:
    //            the warp already holds the full row in registers) ----------
    {
        int r0 = blockIdx.x * 16 + wp * 2;      // 592*16 = 9472 >= 8192
        if (r0 < NN) {
            int r1 = r0 + 1;
            float4 a0 = k4g[r0 * D4 + lane];
            float4 b0 = k4g[r0 * D4 + 32 + lane];
            float4 a1 = k4g[r1 * D4 + lane];
            float4 b1 = k4g[r1 * D4 + 32 + lane];
            // default fused = kernels (fixed up later only if dirty)
            out4[r0 * D4 + lane]      = a0;
            out4[r0 * D4 + 32 + lane] = b0;
            out4[r1 * D4 + lane]      = a1;
            out4[r1 * D4 + 32 + lane] = b1;
            float asq0 = a0.x*a0.x + a0.y*a0.y + a0.z*a0.z + a0.w*a0.w;
            float bsq0 = b0.x*b0.x + b0.y*b0.y + b0.z*b0.z + b0.w*b0.w;
            float asq1 = a1.x*a1.x + a1.y*a1.y + a1.z*a1.z + a1.w*a1.w;
            float bsq1 = b1.x*b1.x + b1.y*b1.y + b1.z*b1.z + b1.w*b1.w;
            float s0 = asq0 + bsq0, s1 = asq1 + bsq1;
            float h0 = (lane < H4) ? asq0 : 0.0f;   // head = dims 0..63
            float h1 = (lane < H4) ? asq1 : 0.0f;
            #pragma unroll
            for (int o = 16; o; o >>= 1) {
                s0 += __shfl_xor_sync(0xFFFFFFFFu, s0, o);
                s1 += __shfl_xor_sync(0xFFFFFFFFu, s1, o);
                h0 += __shfl_xor_sync(0xFFFFFFFFu, h0, o);
                h1 += __shfl_xor_sync(0xFFFFFFFFu, h1, o);
            }
            if (lane < 2) {
                int row = (lane == 0) ? r0 : r1;
                float s = (lane == 0) ? s0 : s1;
                float h = (lane == 0) ? h0 : h1;
                float invn = 1.0f / fmaxf(sqrtf(s), EPSN);
                g_invn[row]  = invn;
                float headfrac = h * invn * invn;
                g_tail[row]  = sqrtf(fmaxf(0.0f, 1.0f - headfrac));
                g_claim[row] = row;
                g_cnt2[row]  = 0;
                // default tail outputs (keep=true); fixed up only if dirty
                out[NN * DD + row]          = (float)cat[row];
                out[NN * DD + NN + row]     = scores[row];
                out[NN * DD + 2 * NN + row] = 1.0f;
                int ci = clamp_cat(cat[row]);
                int pos = atomicAdd(&g_cnt[ci], 1);
                g_buck[ci * NN + pos] = row;
            }
        }
    }
    gbar();

    // ---------- P3: pair tiles, static assignment + binary-search decode ----------
    {
        __shared__ int s_cnt[NC], s_tp[NC + 1];
        __shared__ int wsp[8];
        {
            int c = 0, tp = 0;
            if (t < NC) {
                c = __ldcg(&g_cnt[t]);
                int T = (c + TS - 1) / TS;
                tp = T * (T + 1) / 2;
                s_cnt[t] = c;
            }
            int ip = tp;
            #pragma unroll
            for (int o = 1; o < 32; o <<= 1) {
                int v = __shfl_up_sync(0xFFFFFFFFu, ip, o);
                if (lane >= o) ip += v;
            }
            if (lane == 31 && wp < 4) wsp[wp] = ip;
            __syncthreads();
            if (t < NC) {
                int op = 0;
                #pragma unroll
                for (int ww = 0; ww < 4; ww++)
                    if (ww < wp) op += wsp[ww];
                s_tp[t] = ip + op - tp;   // exclusive prefix
                if (t == NC - 1) s_tp[NC] = ip + op;
            }
            __syncthreads();
        }
        const int total = s_tp[NC];

        float4* sA = sm;
        float4* sB = sm + TS * PH;
        __shared__ int gA[TS], gB[TS];
        __shared__ float sTailA[TS], sTailB[TS];

        for (int w = blockIdx.x; w < total; w += GRID) {
            int lo = 0, hi = NC;
            #pragma unroll
            for (int it = 0; it < 7; it++) {
                int mid = (lo + hi) >> 1;
                if (w >= s_tp[mid]) lo = mid; else hi = mid;
            }
            int c = lo;
            int p = w - s_tp[c];
            int cc = s_cnt[c];
            int T = (cc + TS - 1) / TS;
            int ta = 0;
            while (p >= T - ta) { p -= T - ta; ta++; }
            int tb = ta + p;
            int rowA = c * NN + ta * TS;
            int rowB = c * NN + tb * TS;
            int na = min(TS, cc - ta * TS);
            int nb = min(TS, cc - tb * TS);

            if (t < TS) {
                int a = (t < na) ? __ldcg(&g_buck[rowA + t]) : -1;
                int b = (t < nb) ? __ldcg(&g_buck[rowB + t]) : -1;
                gA[t] = a; gB[t] = b;
                sTailA[t] = (a >= 0) ? g_tail[a] : 0.0f;
                sTailB[t] = (b >= 0) ? g_tail[b] : 0.0f;
            }
            __syncthreads();

            // stage normalized 64-dim heads (2 float4 per thread)
            for (int i = t; i < TS * H4; i += NT) {
                int r = i >> 4, k4 = i & 15;
                float4 va = make_float4(0.f, 0.f, 0.f, 0.f);
                int g = gA[r];
                if (g >= 0) {
                    va = k4g[g * D4 + k4];
                    float sc = g_invn[g];
                    va.x *= sc; va.y *= sc; va.z *= sc; va.w *= sc;
                }
                sA[r * PH + k4] = va;
                float4 vb = make_float4(0.f, 0.f, 0.f, 0.f);
                g = gB[r];
                if (g >= 0) {
                    vb = k4g[g * D4 + k4];
                    float sc = g_invn[g];
                    vb.x *= sc; vb.y *= sc; vb.z *= sc; vb.w *= sc;
                }
                sB[r * PH + k4] = vb;
            }
            __syncthreads();

            int ra = t & 31;
            int rq = t >> 5;
            float a0 = 0.f, a1 = 0.f, a2 = 0.f, a3 = 0.f;
            #pragma unroll
            for (int k4 = 0; k4 < H4; k4++) {
                float4 a  = sA[ra * PH + k4];
                float4 b0 = sB[(rq      ) * PH + k4];
                float4 b1 = sB[(rq +  8 ) * PH + k4];
                float4 b2 = sB[(rq + 16 ) * PH + k4];
                float4 b3 = sB[(rq + 24 ) * PH + k4];
                a0 += a.x * b0.x + a.y * b0.y + a.z * b0.z + a.w * b0.w;
                a1 += a.x * b1.x + a.y * b1.y + a.z * b1.z + a.w * b1.w;
                a2 += a.x * b2.x + a.y * b2.y + a.z * b2.z + a.w * b2.w;
                a3 += a.x * b3.x + a.y * b3.y + a.z * b3.z + a.w * b3.w;
            }
            if (ra < na) {
                int ga = gA[ra];
                float tA = sTailA[ra];
                float accs[4] = {a0, a1, a2, a3};
                #pragma unroll
                for (int j = 0; j < 4; j++) {
                    int rb = rq + 8 * j;
                    if (rb < nb) {
                        int gb = gB[rb];
                        if (gb != ga && accs[j] + tA * sTailB[rb] >= THRESH) {
                            // C-S bound passed: exact full 256-dim dot from L2
                            float invA = g_invn[ga], invB = g_invn[gb];
                            float d = 0.0f;
                            for (int k = 0; k < D4; k++) {
                                float4 x = __ldg(&k4g[ga * D4 + k]);
                                float4 y = __ldg(&k4g[gb * D4 + k]);
                                d += x.x * y.x + x.y * y.y + x.z * y.z + x.w * y.w;
                            }
                            if (d * invA * invB >= THRESH) {
                                int lo2 = min(ga, gb), hi2 = max(ga, gb);
                                atomicMin(&g_claim[hi2], lo2);
                                g_dirty = 1;
                            }
                        }
                    }
                }
            }
            __syncthreads();
        }
    }
    gbar();

    // dirty is FINAL and uniform across blocks here
    const int dirty = __ldcg(&g_dirty);

    if (!dirty) {
        // FAST PATH: defaults written in P0 are exact. Just restore invariants.
        if (blockIdx.x == 1 && t < NC) g_cnt[t] = 0;
        return;
    }

    // ---------- SLOW PATH (rare): fix up affected rows only ----------
    {
        int idx = blockIdx.x * NT + t;
        if (idx < NN) {
            int c = __ldcg(&g_claim[idx]);
            bool keep = (c == idx);
            bool owner_kept = (__ldcg(&g_claim[c]) == c);
            if (owner_kept) atomicAdd(&g_cnt2[c], 1);
            if (!keep) {
                out[NN * DD + idx]          = -1.0f;
                out[NN * DD + NN + idx]     = 0.0f;
                out[NN * DD + 2 * NN + idx] = 0.0f;
                float4 z = make_float4(0.f, 0.f, 0.f, 0.f);
                #pragma unroll 4
                for (int k = 0; k < D4; k++) out4[idx * D4 + k] = z;
                if (owner_kept) {
                    // owner row gets accumulated next phase -> zero it now
                    #pragma unroll 4
                    for (int k = 0; k < D4; k++) out4[c * D4 + k] = z;
                }
            }
        }
    }
    gbar();
    {
        for (int j = blockIdx.x * 8 + wp; j < NN; j += GRID * 8) {
            int i = 0, n = 0;
            if (lane == 0) {
                i = __ldcg(&g_claim[j]);
                n = (__ldcg(&g_claim[i]) == i) ? __ldcg(&g_cnt2[i]) : 0;
            }
            i = __shfl_sync(0xFFFFFFFFu, i, 0);
            n = __shfl_sync(0xFFFFFFFFu, n, 0);
            if (n <= 1) continue;   // n==1 singleton already correct; n==0 owner dropped
            float4 v0 = k4g[j * D4 + lane];
            float4 v1 = k4g[j * D4 + 32 + lane];
            float w = 1.0f / (float)n;
            atomicAdd(&out[i * DD + lane * 4 + 0],       v0.x * w);
            atomicAdd(&out[i * DD + lane * 4 + 1],       v0.y * w);
            atomicAdd(&out[i * DD + lane * 4 + 2],       v0.z * w);
            atomicAdd(&out[i * DD + lane * 4 + 3],       v0.w * w);
            atomicAdd(&out[i * DD + 128 + lane * 4 + 0], v1.x * w);
            atomicAdd(&out[i * DD + 128 + lane * 4 + 1], v1.y * w);
            atomicAdd(&out[i * DD + 128 + lane * 4 + 2], v1.z * w);
            atomicAdd(&out[i * DD + 128 + lane * 4 + 3], v1.w * w);
        }
        // restore invariants (g_dirty consumed by all blocks before previous gbar)
        if (blockIdx.x == 0 && t == 0) g_dirty = 0;
        if (blockIdx.x == 1 && t < NC) g_cnt[t] = 0;
    }
}

// ---------------- launch ----------------
extern "C" void kernel_launch(void* const* d_in, const int* in_sizes, int n_in,
                              void* d_out, int out_size) {
    const float* kin    = (const float*)d_in[0];
    const int*   cat    = (const int*)d_in[1];
    const float* scores = (const float*)d_in[2];
    float*       out    = (float*)d_out;

    (void)in_sizes; (void)n_in; (void)out_size;

    const int smem = 2 * TS * PH * (int)sizeof(float4);  // 17,408 B
    cudaFuncSetAttribute(k_all, cudaFuncAttributeMaxDynamicSharedMemorySize, smem);

    k_all<<<GRID, NT, smem>>>(kin, cat, scores, out);
}